// round 11
// baseline (speedup 1.0000x reference)
#include <cuda_runtime.h>
#include <cstdint>

// Problem constants
#define BATCH   256
#define UNITS   256
#define DZ      128
#define DX      128
#define TST     1024
#define NG      1024   // 4*UNITS gate columns
#define KTOT    512    // z(128) + x(128) + h(256)

#define NCTA    128
#define NTHR    512
#define CPG     16     // CTAs per batch group
#define NGRP    8      // batch groups
#define GB      32     // batch rows per group

// ---------------- persistent device state ----------------
__device__ float g_H[2][BATCH * UNITS];
__device__ float g_Z[BATCH * DZ];
__device__ unsigned          g_cnt[NGRP * 32];   // padded to 128B per group
__device__ volatile unsigned g_gen[NGRP * 32];
__device__ unsigned          g_done[NGRP * 32];

// ---------------- packed f32x2 helpers ----------------
typedef unsigned long long ull;
__device__ __forceinline__ ull pack2(float x, float y) {
    ull r; asm("mov.b64 %0, {%1, %2};" : "=l"(r) : "f"(x), "f"(y)); return r;
}
__device__ __forceinline__ void unpack2(ull v, float& x, float& y) {
    asm("mov.b64 {%0, %1}, %2;" : "=f"(x), "=f"(y) : "l"(v));
}
__device__ __forceinline__ void ffma2(ull& d, ull a, ull b) {
    asm("fma.rn.f32x2 %0, %1, %2, %0;" : "+l"(d) : "l"(a), "l"(b));
}
__device__ __forceinline__ void fadd2(ull& d, ull a) {
    asm("add.rn.f32x2 %0, %0, %1;" : "+l"(d) : "l"(a));
}
__device__ __forceinline__ float ld_cg(const float* p) {
    float v; asm volatile("ld.global.cg.f32 %0, [%1];" : "=f"(v) : "l"(p)); return v;
}
__device__ __forceinline__ void st_cg(float* p, float v) {
    asm volatile("st.global.cg.f32 [%0], %1;" :: "l"(p), "f"(v));
}
__device__ __forceinline__ float sigmoidf_acc(float x) {
    return 1.0f / (1.0f + expf(-x));
}

// ---------------- group barrier (16 CTAs, monotonic target) ----------------
__device__ __forceinline__ void group_sync(int grp, unsigned target) {
    __syncthreads();
    if (threadIdx.x == 0) {
        __threadfence();
        unsigned a = atomicAdd(&g_cnt[grp * 32], 1u) + 1u;
        if (a == (unsigned)CPG * target) {
            __threadfence();
            g_gen[grp * 32] = target;
        } else {
            while (g_gen[grp * 32] < target) { }
        }
        __threadfence();
    }
    __syncthreads();
}

// SMEM layout (floats):
//   Wg : [512][64]   gate weights, persistent         @ 0       (32768)
//   W2 : [16][260]   head weights, persistent         @ 32768   (4160)
//   S  : [512][36]   s-tile (transposed) / partials / h-tile  @ 36928 (18432)
//   EX : [32][8]     sigma exchange                   @ 55360   (256)
#define WG_OFF 0
#define W2_OFF 32768
#define S_OFF  36928
#define EX_OFF 55360
#define SM_FLOATS 55616           // 222464 bytes

__global__ void __launch_bounds__(NTHR, 1) fused_lstm_persistent(
    const float* __restrict__ inputs,   // [B, T, DX]
    const float* __restrict__ Wk,       // [256, 1024]
    const float* __restrict__ Wr,       // [256, 1024]
    const float* __restrict__ bias,     // [1024]
    const float* __restrict__ Wmu,      // [256, 128]
    const float* __restrict__ bmu,      // [128]
    const float* __restrict__ Wsg,      // [256, 128]
    const float* __restrict__ bsg,      // [128]
    const float* __restrict__ eps,      // [T-1, B, DZ]
    float* __restrict__ out)            // mu [B,T,DZ] ++ sigma [B,T,DZ]
{
    extern __shared__ float sm[];
    float* Wg = sm + WG_OFF;
    float* W2 = sm + W2_OFF;
    float* S  = sm + S_OFF;
    float* EX = sm + EX_OFF;

    const int tid = threadIdx.x;
    const int cta = blockIdx.x;
    const int grp = cta >> 4;          // batch group 0..7
    const int cg  = cta & 15;          // CTA index within group
    const int gb0 = grp * GB;          // first batch row of group
    const int u0  = cg * 16;           // first unit of this CTA's gate slice

    // ---- one-time staging: gate weights [k][u*4+g] ----
    for (int i = tid; i < 512 * 16; i += NTHR) {
        const int k = i >> 4, uu = i & 15;
        const float* src = (k < 256) ? (Wk + (size_t)k * NG)
                                     : (Wr + (size_t)(k - 256) * NG);
        #pragma unroll
        for (int g = 0; g < 4; ++g)
            Wg[k * 64 + uu * 4 + g] = src[g * 256 + u0 + uu];
    }
    // ---- one-time staging: head weights, rows r=(j*2+head), cols k ----
    for (int i = tid; i < 16 * 256; i += NTHR) {
        const int r = i >> 8, k = i & 255;
        const int j = r >> 1, head = r & 1;
        const int zc = cg * 8 + j;
        W2[r * 260 + k] = head ? Wsg[(size_t)k * DZ + zc]
                               : Wmu[(size_t)k * DZ + zc];
    }
    // ---- zero initial state for this group's rows ----
    g_H[0][gb0 * UNITS + cg * 512 + tid] = 0.0f;        // 16*512 = 32*256
    if (tid < 256) g_Z[gb0 * DZ + cg * 256 + tid] = 0.0f;

    // ---- phase-1 mainloop identity: warp = (ks, upart); lane = (uu, bg) ----
    const int warp = tid >> 5, lane = tid & 31;
    const int ks     = warp >> 1;                 // k-split 0..7 (64 k each)
    const int ulocal = (warp & 1) * 8 + ((lane >> 2) & 7);
    const int b8     = (lane & 3) * 8;            // first of 8 batch rows
    const int k0     = ks * 64;

    // ---- reducer identity (tid < 256): owns (b-pair rbp, unit ru) ----
    const int rbp = tid >> 4;                     // 0..15 b-pairs
    const int ru  = tid & 15;
    const int rug = u0 + ru;
    float bi = 0.f, bf = 0.f, bg_ = 0.f, bo = 0.f;
    if (tid < 256) {
        bi  = bias[rug];       bf = bias[256 + rug];
        bg_ = bias[512 + rug]; bo = bias[768 + rug];
    }
    // partner base for k-split reduction: partner(ks) layout in partials
    const int partner0 = ((ru >> 3) * 32) + ((ru & 7) * 4) + (rbp >> 2);
    const float* rbase = S + partner0 * 36 + (rbp & 3) * 8;
    float c0 = 0.0f, c1 = 0.0f;                   // cell state (register resident)

    // ---- phase-2 identity: thread = (pb, pj, ph) ----
    const int pb  = tid >> 4;                     // 0..31 batch row in group
    const int pj  = (tid >> 1) & 7;               // z-col within CTA slice
    const int ph  = tid & 1;                      // 0 = mu, 1 = sigma
    const int prow = (pj << 1) | ph;
    const int pzc  = cg * 8 + pj;                 // global z column
    const float bh = ph ? bsg[pzc] : bmu[pzc];
    const int pbg  = gb0 + pb;

    unsigned nbar = 0;
    group_sync(grp, ++nbar);

    for (int t = 0; t < TST; ++t) {
        const float* __restrict__ Hin  = g_H[t & 1];
        float* __restrict__       Hout = g_H[(t & 1) ^ 1];

        // ============ PHASE 1a: stage s = [z|x|h] transposed S[k][b] ============
        {
            const int k = tid;
            float* dst = S + k * 36;
            if (k < 128) {
                const float* zsrc = g_Z + gb0 * DZ + k;
                #pragma unroll 8
                for (int r = 0; r < 32; ++r) dst[r] = ld_cg(zsrc + r * DZ);
            } else if (k < 256) {
                const float* xsrc = inputs + (size_t)gb0 * (TST * DX)
                                           + (size_t)t * DX + (k - 128);
                #pragma unroll 8
                for (int r = 0; r < 32; ++r)
                    dst[r] = __ldg(xsrc + (size_t)r * (TST * DX));
            } else {
                const float* hsrc = Hin + gb0 * UNITS + (k - 256);
                #pragma unroll 8
                for (int r = 0; r < 32; ++r) dst[r] = ld_cg(hsrc + r * UNITS);
            }
        }
        __syncthreads();

        // ============ PHASE 1b: register-blocked gates GEMM (8b x 4g x 64k) =====
        ull a[16];
        #pragma unroll
        for (int i = 0; i < 16; ++i) a[i] = 0ULL;
        {
            const float* wptr = Wg + k0 * 64 + ulocal * 4;
            const float* sptr = S + k0 * 36 + b8;
            #pragma unroll 2
            for (int kk = 0; kk < 64; ++kk) {
                const float4 w4 = *reinterpret_cast<const float4*>(wptr);
                const ulonglong2 sA = *reinterpret_cast<const ulonglong2*>(sptr);
                const ulonglong2 sB = *reinterpret_cast<const ulonglong2*>(sptr + 4);
                wptr += 64; sptr += 36;
                const ull d0 = pack2(w4.x, w4.x);
                const ull d1 = pack2(w4.y, w4.y);
                const ull d2 = pack2(w4.z, w4.z);
                const ull d3 = pack2(w4.w, w4.w);
                ffma2(a[0],  sA.x, d0); ffma2(a[1],  sA.x, d1);
                ffma2(a[2],  sA.x, d2); ffma2(a[3],  sA.x, d3);
                ffma2(a[4],  sA.y, d0); ffma2(a[5],  sA.y, d1);
                ffma2(a[6],  sA.y, d2); ffma2(a[7],  sA.y, d3);
                ffma2(a[8],  sB.x, d0); ffma2(a[9],  sB.x, d1);
                ffma2(a[10], sB.x, d2); ffma2(a[11], sB.x, d3);
                ffma2(a[12], sB.y, d0); ffma2(a[13], sB.y, d1);
                ffma2(a[14], sB.y, d2); ffma2(a[15], sB.y, d3);
            }
        }
        __syncthreads();     // all S reads done -> reuse region for partials

        // write partials: 16 u64 per thread at stride 36 floats
        {
            float* dst = S + tid * 36;
            #pragma unroll
            for (int i = 0; i < 8; ++i) {
                ulonglong2 v; v.x = a[2 * i]; v.y = a[2 * i + 1];
                *reinterpret_cast<ulonglong2*>(dst + i * 4) = v;
            }
        }
        __syncthreads();

        // ============ PHASE 1c: K-split reduction + LSTM update (tid<256) ======
        if (tid < 256) {
            ull r0 = 0ULL, r1 = 0ULL, r2 = 0ULL, r3 = 0ULL;
            const float* p = rbase;
            #pragma unroll
            for (int s = 0; s < 8; ++s) {
                const ulonglong2 q0 = *reinterpret_cast<const ulonglong2*>(p);
                const ulonglong2 q1 = *reinterpret_cast<const ulonglong2*>(p + 4);
                fadd2(r0, q0.x); fadd2(r1, q0.y);
                fadd2(r2, q1.x); fadd2(r3, q1.y);
                p += 2 * 32 * 36;       // next k-split partner
            }
            float i0, i1, f0, f1, gg0, gg1, o0, o1;
            unpack2(r0, i0, i1); unpack2(r1, f0, f1);
            unpack2(r2, gg0, gg1); unpack2(r3, o0, o1);

            c0 = sigmoidf_acc(f0 + bf) * c0 + sigmoidf_acc(i0 + bi) * tanhf(gg0 + bg_);
            c1 = sigmoidf_acc(f1 + bf) * c1 + sigmoidf_acc(i1 + bi) * tanhf(gg1 + bg_);
            const float h0 = sigmoidf_acc(o0 + bo) * tanhf(c0);
            const float h1 = sigmoidf_acc(o1 + bo) * tanhf(c1);
            const int bG = gb0 + rbp * 2;
            st_cg(Hout + (size_t)bG * UNITS + rug, h0);
            st_cg(Hout + (size_t)(bG + 1) * UNITS + rug, h1);
        }

        group_sync(grp, ++nbar);   // H visible group-wide

        // ============ PHASE 2: heads + sample + output ============
        // stage h tile [32][260]
        for (int i = tid; i < 32 * 256; i += NTHR) {
            const int r = i >> 8, col = i & 255;
            S[r * 260 + col] = ld_cg(Hout + (size_t)(gb0 + r) * UNITS + col);
        }
        __syncthreads();

        ull acc = 0ULL;
        {
            const float* hr = S + pb * 260;
            const float* wr = W2 + prow * 260;
            #pragma unroll 4
            for (int k = 0; k < 256; k += 4) {
                const ulonglong2 hp = *reinterpret_cast<const ulonglong2*>(hr + k);
                const ulonglong2 wp = *reinterpret_cast<const ulonglong2*>(wr + k);
                ffma2(acc, hp.x, wp.x);
                ffma2(acc, hp.y, wp.y);
            }
        }
        float lo, hi; unpack2(acc, lo, hi);
        float val = lo + hi + bh;
        if (ph) val = fmaxf(val, 0.0f) + log1pf(expf(-fabsf(val))) + 1e-6f;

        const size_t ob = (size_t)pbg * (TST * DZ) + (size_t)t * DZ + pzc;
        if (ph) out[(size_t)BATCH * TST * DZ + ob] = val;
        else    out[ob] = val;

        if (ph) EX[pb * 8 + pj] = val;
        __syncthreads();
        if (!ph && t < TST - 1) {
            const float sg = EX[pb * 8 + pj];
            const float e  = __ldg(eps + (size_t)t * (BATCH * DZ)
                                       + (size_t)pbg * DZ + pzc);
            st_cg(g_Z + pbg * DZ + pzc, fmaf(sg, e, val));
        }

        group_sync(grp, ++nbar);   // z visible group-wide
    }

    // ---- reset barrier state for next graph replay (last-arriver protocol) ----
    if (tid == 0) {
        __threadfence();
        const unsigned d = atomicAdd(&g_done[grp * 32], 1u) + 1u;
        if (d == CPG) {
            g_cnt[grp * 32]  = 0;
            g_done[grp * 32] = 0;
            g_gen[grp * 32]  = 0;
            __threadfence();
        }
    }
}

extern "C" void kernel_launch(void* const* d_in, const int* in_sizes, int n_in,
                              void* d_out, int out_size) {
    (void)in_sizes; (void)n_in; (void)out_size;
    const float* inputs = (const float*)d_in[0];
    const float* Wk     = (const float*)d_in[1];
    const float* Wr     = (const float*)d_in[2];
    const float* bias   = (const float*)d_in[3];
    const float* Wmu    = (const float*)d_in[4];
    const float* bmu    = (const float*)d_in[5];
    const float* Wsg    = (const float*)d_in[6];
    const float* bsg    = (const float*)d_in[7];
    const float* eps    = (const float*)d_in[8];
    float* out          = (float*)d_out;

    const size_t smem_bytes = (size_t)SM_FLOATS * sizeof(float);  // 222464 B
    cudaFuncSetAttribute(fused_lstm_persistent,
                         cudaFuncAttributeMaxDynamicSharedMemorySize,
                         (int)smem_bytes);

    fused_lstm_persistent<<<NCTA, NTHR, smem_bytes>>>(
        inputs, Wk, Wr, bias, Wmu, bmu, Wsg, bsg, eps, out);
}

// round 15
// speedup vs baseline: 1.0606x; 1.0606x over previous
#include <cuda_runtime.h>
#include <cstdint>

// Problem constants
#define BATCH   256
#define UNITS   256
#define DZ      128
#define DX      128
#define TST     1024
#define NG      1024   // 4*UNITS gate columns
#define KTOT    512    // z(128) + x(128) + h(256)

#define NCTA    128
#define NTHR    512
#define NPG     4      // pair-groups (64 batch rows each)
#define CPG     32     // CTAs per pair-group
#define NBSLOT  (NPG*2)

// ---------------- persistent device state ----------------
__device__ float g_H[2][BATCH * UNITS];
__device__ float g_Z[BATCH * DZ];
__device__ unsigned          g_cnt[NBSLOT * 32];   // one 128B line per (pg, half)
__device__ volatile unsigned g_gen[NBSLOT * 32];
__device__ unsigned          g_done[NBSLOT * 32];

// ---------------- packed f32x2 helpers ----------------
typedef unsigned long long ull;
__device__ __forceinline__ ull pack2(float x, float y) {
    ull r; asm("mov.b64 %0, {%1, %2};" : "=l"(r) : "f"(x), "f"(y)); return r;
}
__device__ __forceinline__ void unpack2(ull v, float& x, float& y) {
    asm("mov.b64 {%0, %1}, %2;" : "=f"(x), "=f"(y) : "l"(v));
}
__device__ __forceinline__ void ffma2(ull& d, ull a, ull b) {
    asm("fma.rn.f32x2 %0, %1, %2, %0;" : "+l"(d) : "l"(a), "l"(b));
}
__device__ __forceinline__ void fadd2(ull& d, ull a) {
    asm("add.rn.f32x2 %0, %0, %1;" : "+l"(d) : "l"(a));
}
__device__ __forceinline__ float ld_cg(const float* p) {
    float v; asm volatile("ld.global.cg.f32 %0, [%1];" : "=f"(v) : "l"(p)); return v;
}
__device__ __forceinline__ float4 ld_cg_f4(const float* p) {
    float4 v;
    asm volatile("ld.global.cg.v4.f32 {%0,%1,%2,%3}, [%4];"
                 : "=f"(v.x), "=f"(v.y), "=f"(v.z), "=f"(v.w) : "l"(p));
    return v;
}
__device__ __forceinline__ void st_cg(float* p, float v) {
    asm volatile("st.global.cg.f32 [%0], %1;" :: "l"(p), "f"(v));
}
__device__ __forceinline__ float sigmoidf_acc(float x) {
    return 1.0f / (1.0f + expf(-x));
}

// named barrier over one 256-thread half
__device__ __forceinline__ void hbar(int id) {
    asm volatile("bar.sync %0, 256;" :: "r"(id) : "memory");
}

// 32-CTA group barrier for one half (monotonic target)
__device__ __forceinline__ void group_sync(int bslot, int barid, int ltid, unsigned target) {
    hbar(barid);
    if (ltid == 0) {
        __threadfence();
        unsigned a = atomicAdd(&g_cnt[bslot], 1u) + 1u;
        if (a == (unsigned)CPG * target) {
            __threadfence();
            g_gen[bslot] = target;
        } else {
            while (g_gen[bslot] < target) { }
        }
        __threadfence();
    }
    hbar(barid);
}

// SMEM layout (floats):
//   Wg  : [512][32]  gate weights (8 units x 4 gates), persistent   @ 0      (16384)
//   W2  : [8][260]   head weights (4 z x {mu,sig}), persistent      @ 16384  (2080)
//   S_A : [512][36]  half-A s-tile / partials / h-tile              @ 18464  (18432)
//   S_B : [512][36]  half-B                                          @ 36896  (18432)
//   EX_A: [32][4]    sigma exchange half A                           @ 55328  (128)
//   EX_B: [32][4]                                                    @ 55456  (128)
#define WG_OFF  0
#define W2_OFF  16384
#define SA_OFF  18464
#define SB_OFF  36896
#define EXA_OFF 55328
#define EXB_OFF 55456
#define SM_FLOATS 55584      // 222336 bytes

__global__ void __launch_bounds__(NTHR, 1) fused_lstm_persistent(
    const float* __restrict__ inputs,   // [B, T, DX]
    const float* __restrict__ Wk,       // [256, 1024]
    const float* __restrict__ Wr,       // [256, 1024]
    const float* __restrict__ bias,     // [1024]
    const float* __restrict__ Wmu,      // [256, 128]
    const float* __restrict__ bmu,      // [128]
    const float* __restrict__ Wsg,      // [256, 128]
    const float* __restrict__ bsg,      // [128]
    const float* __restrict__ eps,      // [T-1, B, DZ]
    float* __restrict__ out)            // mu [B,T,DZ] ++ sigma [B,T,DZ]
{
    extern __shared__ float sm[];
    float* Wg = sm + WG_OFF;
    float* W2 = sm + W2_OFF;

    const int tid = threadIdx.x;
    const int cta = blockIdx.x;
    const int pg  = cta >> 5;          // pair-group 0..3 (64 batch rows)
    const int cgi = cta & 31;          // CTA index in group (unit slice)
    const int u0  = cgi * 8;           // 8 units per CTA

    const int h     = tid >> 8;        // half 0 / 1
    const int ltid  = tid & 255;
    const int barid = 1 + h;
    const int bslot = (pg * 2 + h) * 32;
    const int hb0   = pg * 64 + h * 32;   // first batch row of this half

    float* S  = sm + (h ? SB_OFF : SA_OFF);
    float* EX = sm + (h ? EXB_OFF : EXA_OFF);

    // ---- one-time: stage gate weights [k][uu*4+g] (whole CTA) ----
    for (int i = tid; i < 512 * 8; i += NTHR) {
        const int k = i >> 3, uu = i & 7;
        const float* src = (k < 256) ? (Wk + (size_t)k * NG)
                                     : (Wr + (size_t)(k - 256) * NG);
        #pragma unroll
        for (int g = 0; g < 4; ++g)
            Wg[k * 32 + uu * 4 + g] = src[g * 256 + u0 + uu];
    }
    // ---- one-time: head weights, rows r = pj*2+head ----
    for (int i = tid; i < 8 * 256; i += NTHR) {
        const int r = i >> 8, k = i & 255;
        const int j = r >> 1, head = r & 1;
        const int zc = cgi * 4 + j;
        W2[r * 260 + k] = head ? Wsg[(size_t)k * DZ + zc]
                               : Wmu[(size_t)k * DZ + zc];
    }
    // ---- zero init (group-local slices so the group barrier covers them) ----
    g_H[0][pg * 64 * UNITS + cgi * 512 + tid] = 0.0f;
    if (tid < 256) g_Z[pg * 64 * DZ + cgi * 256 + tid] = 0.0f;
    __syncthreads();

    // ---- phase-1 mainloop identity: warp-in-half = k-split ----
    const int wih    = (tid >> 5) & 7;          // ks 0..7
    const int lane   = tid & 31;
    const int ulocal = lane >> 2;               // 0..7
    const int b8     = (lane & 3) * 8;          // 0,8,16,24
    const int k0     = wih * 64;

    // ---- reducer identity (ltid < 128): (b-pair, unit) ----
    const int rbp = ltid >> 3;                  // 0..15
    const int ru  = ltid & 7;                   // 0..7
    const int rug = u0 + ru;
    float bi = 0.f, bf = 0.f, bg_ = 0.f, bo = 0.f;
    if (ltid < 128) {
        bi  = bias[rug];       bf = bias[256 + rug];
        bg_ = bias[512 + rug]; bo = bias[768 + rug];
    }
    const float* rbase = S + (ru * 4 + (rbp >> 2)) * 36 + (rbp & 3) * 8;
    float c0 = 0.0f, c1 = 0.0f;                 // cell state, register resident

    // ---- phase-2 identity: (pb, pj, ph) ----
    const int pb   = ltid >> 3;                 // 0..31
    const int pj   = (ltid >> 1) & 3;           // 0..3
    const int ph   = ltid & 1;                  // 0=mu, 1=sigma
    const int prow = pj * 2 + ph;
    const int pzc  = cgi * 4 + pj;
    const float bh = ph ? bsg[pzc] : bmu[pzc];
    const int pbg  = hb0 + pb;

    unsigned nb = 0;
    group_sync(bslot, barid, ltid, ++nb);

    for (int t = 0; t < TST; ++t) {
        const float* __restrict__ Hin  = g_H[t & 1];
        float* __restrict__       Hout = g_H[(t & 1) ^ 1];

        // ============ PHASE 1a: stage s = [z|x|h] transposed S[k][b] ============
        #pragma unroll
        for (int pass = 0; pass < 2; ++pass) {
            const int k = ltid + pass * 256;
            float* dst = S + k * 36;
            if (k < 128) {
                const float* src = g_Z + hb0 * DZ + k;
                #pragma unroll
                for (int r4 = 0; r4 < 32; r4 += 4) {
                    float4 v;
                    v.x = ld_cg(src + (r4 + 0) * DZ);
                    v.y = ld_cg(src + (r4 + 1) * DZ);
                    v.z = ld_cg(src + (r4 + 2) * DZ);
                    v.w = ld_cg(src + (r4 + 3) * DZ);
                    *reinterpret_cast<float4*>(dst + r4) = v;
                }
            } else if (k < 256) {
                const float* src = inputs + (size_t)hb0 * (TST * DX)
                                          + (size_t)t * DX + (k - 128);
                #pragma unroll
                for (int r4 = 0; r4 < 32; r4 += 4) {
                    float4 v;
                    v.x = __ldg(src + (size_t)(r4 + 0) * (TST * DX));
                    v.y = __ldg(src + (size_t)(r4 + 1) * (TST * DX));
                    v.z = __ldg(src + (size_t)(r4 + 2) * (TST * DX));
                    v.w = __ldg(src + (size_t)(r4 + 3) * (TST * DX));
                    *reinterpret_cast<float4*>(dst + r4) = v;
                }
            } else {
                const float* src = Hin + hb0 * UNITS + (k - 256);
                #pragma unroll
                for (int r4 = 0; r4 < 32; r4 += 4) {
                    float4 v;
                    v.x = ld_cg(src + (r4 + 0) * UNITS);
                    v.y = ld_cg(src + (r4 + 1) * UNITS);
                    v.z = ld_cg(src + (r4 + 2) * UNITS);
                    v.w = ld_cg(src + (r4 + 3) * UNITS);
                    *reinterpret_cast<float4*>(dst + r4) = v;
                }
            }
        }
        hbar(barid);

        // ============ PHASE 1b: register-blocked gates GEMM (8b x 4g x 64k) =====
        ull a[16];
        #pragma unroll
        for (int i = 0; i < 16; ++i) a[i] = 0ULL;
        {
            const float* wptr = Wg + k0 * 32 + ulocal * 4;
            const float* sptr = S + k0 * 36 + b8;
            #pragma unroll 2
            for (int kk = 0; kk < 64; ++kk) {
                const float4 w4 = *reinterpret_cast<const float4*>(wptr);
                const ulonglong2 sA = *reinterpret_cast<const ulonglong2*>(sptr);
                const ulonglong2 sB = *reinterpret_cast<const ulonglong2*>(sptr + 4);
                wptr += 32; sptr += 36;
                const ull d0 = pack2(w4.x, w4.x);
                const ull d1 = pack2(w4.y, w4.y);
                const ull d2 = pack2(w4.z, w4.z);
                const ull d3 = pack2(w4.w, w4.w);
                ffma2(a[0],  sA.x, d0); ffma2(a[1],  sA.x, d1);
                ffma2(a[2],  sA.x, d2); ffma2(a[3],  sA.x, d3);
                ffma2(a[4],  sA.y, d0); ffma2(a[5],  sA.y, d1);
                ffma2(a[6],  sA.y, d2); ffma2(a[7],  sA.y, d3);
                ffma2(a[8],  sB.x, d0); ffma2(a[9],  sB.x, d1);
                ffma2(a[10], sB.x, d2); ffma2(a[11], sB.x, d3);
                ffma2(a[12], sB.y, d0); ffma2(a[13], sB.y, d1);
                ffma2(a[14], sB.y, d2); ffma2(a[15], sB.y, d3);
            }
        }
        hbar(barid);          // all S reads complete -> reuse region for partials

        // write partials: 8 x ulonglong2 at S + ltid*36
        {
            float* dst = S + ltid * 36;
            #pragma unroll
            for (int i = 0; i < 8; ++i) {
                ulonglong2 v; v.x = a[2 * i]; v.y = a[2 * i + 1];
                *reinterpret_cast<ulonglong2*>(dst + i * 4) = v;
            }
        }
        hbar(barid);

        // ============ PHASE 1c: K-split reduction + LSTM update (ltid<128) ======
        if (ltid < 128) {
            ull r0 = 0ULL, r1 = 0ULL, r2 = 0ULL, r3 = 0ULL;
            const float* p = rbase;
            #pragma unroll
            for (int s = 0; s < 8; ++s) {
                const ulonglong2 q0 = *reinterpret_cast<const ulonglong2*>(p);
                const ulonglong2 q1 = *reinterpret_cast<const ulonglong2*>(p + 4);
                fadd2(r0, q0.x); fadd2(r1, q0.y);
                fadd2(r2, q1.x); fadd2(r3, q1.y);
                p += 32 * 36;   // next k-split partner (one warp = 32 threads)
            }
            float i0, i1, f0, f1, gg0, gg1, o0, o1;
            unpack2(r0, i0, i1); unpack2(r1, f0, f1);
            unpack2(r2, gg0, gg1); unpack2(r3, o0, o1);

            c0 = sigmoidf_acc(f0 + bf) * c0 + sigmoidf_acc(i0 + bi) * tanhf(gg0 + bg_);
            c1 = sigmoidf_acc(f1 + bf) * c1 + sigmoidf_acc(i1 + bi) * tanhf(gg1 + bg_);
            const float h0 = sigmoidf_acc(o0 + bo) * tanhf(c0);
            const float h1 = sigmoidf_acc(o1 + bo) * tanhf(c1);
            const int bG = hb0 + rbp * 2;
            st_cg(Hout + (size_t)bG * UNITS + rug, h0);
            st_cg(Hout + (size_t)(bG + 1) * UNITS + rug, h1);
        }

        group_sync(bslot, barid, ltid, ++nb);   // H visible group-wide (this half)

        // ============ PHASE 2: heads + sample + output ============
        #pragma unroll
        for (int pass = 0; pass < 8; ++pass) {
            const int idx = ltid + pass * 256;
            const int r = idx >> 6, c4 = (idx & 63) * 4;
            const float4 v = ld_cg_f4(Hout + (size_t)(hb0 + r) * UNITS + c4);
            *reinterpret_cast<float4*>(S + r * 260 + c4) = v;
        }
        hbar(barid);

        ull acc = 0ULL;
        {
            const float* hr = S + pb * 260;
            const float* wr = W2 + prow * 260;
            #pragma unroll 4
            for (int k = 0; k < 256; k += 4) {
                const ulonglong2 hp = *reinterpret_cast<const ulonglong2*>(hr + k);
                const ulonglong2 wp = *reinterpret_cast<const ulonglong2*>(wr + k);
                ffma2(acc, hp.x, wp.x);
                ffma2(acc, hp.y, wp.y);
            }
        }
        float lo, hi; unpack2(acc, lo, hi);
        float val = lo + hi + bh;
        if (ph) val = fmaxf(val, 0.0f) + log1pf(expf(-fabsf(val))) + 1e-6f;

        const size_t ob = (size_t)pbg * (TST * DZ) + (size_t)t * DZ + pzc;
        if (ph) out[(size_t)BATCH * TST * DZ + ob] = val;
        else    out[ob] = val;

        if (ph) EX[pb * 4 + pj] = val;
        hbar(barid);
        if (!ph && t < TST - 1) {
            const float sg = EX[pb * 4 + pj];
            const float e  = __ldg(eps + (size_t)t * (BATCH * DZ)
                                       + (size_t)pbg * DZ + pzc);
            st_cg(g_Z + pbg * DZ + pzc, fmaf(sg, e, val));
        }

        group_sync(bslot, barid, ltid, ++nb);   // z visible group-wide (this half)
    }

    // ---- reset barrier state for next graph replay (last-arriver protocol) ----
    if (ltid == 0) {
        __threadfence();
        const unsigned d = atomicAdd(&g_done[bslot], 1u) + 1u;
        if (d == CPG) {
            g_cnt[bslot]  = 0;
            g_done[bslot] = 0;
            g_gen[bslot]  = 0;
            __threadfence();
        }
    }
}

extern "C" void kernel_launch(void* const* d_in, const int* in_sizes, int n_in,
                              void* d_out, int out_size) {
    (void)in_sizes; (void)n_in; (void)out_size;
    const float* inputs = (const float*)d_in[0];
    const float* Wk     = (const float*)d_in[1];
    const float* Wr     = (const float*)d_in[2];
    const float* bias   = (const float*)d_in[3];
    const float* Wmu    = (const float*)d_in[4];
    const float* bmu    = (const float*)d_in[5];
    const float* Wsg    = (const float*)d_in[6];
    const float* bsg    = (const float*)d_in[7];
    const float* eps    = (const float*)d_in[8];
    float* out          = (float*)d_out;

    const size_t smem_bytes = (size_t)SM_FLOATS * sizeof(float);  // 222336 B
    cudaFuncSetAttribute(fused_lstm_persistent,
                         cudaFuncAttributeMaxDynamicSharedMemorySize,
                         (int)smem_bytes);

    fused_lstm_persistent<<<NCTA, NTHR, smem_bytes>>>(
        inputs, Wk, Wr, bias, Wmu, bmu, Wsg, bsg, eps, out);
}

// round 16
// speedup vs baseline: 1.1019x; 1.0390x over previous
#include <cuda_runtime.h>
#include <cstdint>

// Problem constants
#define BATCH 256
#define UNITS 256
#define DZ    128
#define DX    128
#define TST   1024
#define NG    1024   // 4*UNITS gate columns
#define NCTA  128
#define NTHR  512
#define CPG   16     // CTAs per group (= cluster size)
#define NGRP  8
#define GB    32     // batch rows per group

// ---------------- persistent device state (transposed layouts) ----------------
__device__ float g_H[UNITS * BATCH];   // [u][b]
__device__ float g_Z[DZ * BATCH];      // [zc][b]
// fallback barrier state (used only when clusters unavailable)
__device__ unsigned          g_cnt[NGRP * 32];
__device__ volatile unsigned g_gen[NGRP * 32];
__device__ unsigned          g_done[NGRP * 32];

// ---------------- packed f32x2 helpers ----------------
typedef unsigned long long ull;
__device__ __forceinline__ ull pack2(float x, float y) {
    ull r; asm("mov.b64 %0, {%1, %2};" : "=l"(r) : "f"(x), "f"(y)); return r;
}
__device__ __forceinline__ void unpack2(ull v, float& x, float& y) {
    asm("mov.b64 {%0, %1}, %2;" : "=f"(x), "=f"(y) : "l"(v));
}
__device__ __forceinline__ void ffma2(ull& d, ull a, ull b) {
    asm("fma.rn.f32x2 %0, %1, %2, %0;" : "+l"(d) : "l"(a), "l"(b));
}
__device__ __forceinline__ void fadd2(ull& d, ull a) {
    asm("add.rn.f32x2 %0, %0, %1;" : "+l"(d) : "l"(a));
}
__device__ __forceinline__ float ld_cg(const float* p) {
    float v; asm volatile("ld.global.cg.f32 %0, [%1];" : "=f"(v) : "l"(p)); return v;
}
__device__ __forceinline__ float4 ld_cg_f4(const float* p) {
    float4 v;
    asm volatile("ld.global.cg.v4.f32 {%0,%1,%2,%3}, [%4];"
                 : "=f"(v.x), "=f"(v.y), "=f"(v.z), "=f"(v.w) : "l"(p));
    return v;
}
__device__ __forceinline__ void st_cg(float* p, float v) {
    asm volatile("st.global.cg.f32 [%0], %1;" :: "l"(p), "f"(v));
}
__device__ __forceinline__ void st_cg_f2(float* p, float a, float b) {
    asm volatile("st.global.cg.v2.f32 [%0], {%1,%2};" :: "l"(p), "f"(a), "f"(b));
}
__device__ __forceinline__ float sigmoidf_acc(float x) {
    return 1.0f / (1.0f + expf(-x));
}

// ---------------- barriers ----------------
__device__ __forceinline__ void cbar_arrive() {
    asm volatile("barrier.cluster.arrive.aligned;" ::: "memory");
}
__device__ __forceinline__ void cbar_wait() {
    asm volatile("barrier.cluster.wait.aligned;" ::: "memory");
}
// fallback: L2 atomic group barrier (monotonic target)
__device__ __forceinline__ void fb_sync(int slot, unsigned target) {
    __syncthreads();
    if (threadIdx.x == 0) {
        __threadfence();
        unsigned a = atomicAdd(&g_cnt[slot], 1u) + 1u;
        if (a == (unsigned)CPG * target) {
            __threadfence();
            g_gen[slot] = target;
        } else {
            while (g_gen[slot] < target) { }
        }
        __threadfence();
    }
    __syncthreads();
}

// SMEM layout (floats):
//   Wg : [512][64]  gate weights [k][u*4+g], persistent   @ 0      (32768)
//   W2 : [16][260]  head weights [zc*2+head][u], persist  @ 32768  (4160)
//   S  : [512][36]  s-tile: z rows 0-127, x 128-255, h 256-511
//        (also aliased: phase1 partials over all rows; phase2 partials rows 0-28)
#define WG_OFF 0
#define W2_OFF 32768
#define S_OFF  36928
#define SM_FLOATS 55360      // 221440 bytes

__global__ void __launch_bounds__(NTHR, 1) fused_lstm_persistent(
    const float* __restrict__ inputs,   // [B, T, DX]
    const float* __restrict__ Wk,       // [256, 1024]
    const float* __restrict__ Wr,       // [256, 1024]
    const float* __restrict__ bias,     // [1024]
    const float* __restrict__ Wmu,      // [256, 128]
    const float* __restrict__ bmu,      // [128]
    const float* __restrict__ Wsg,      // [256, 128]
    const float* __restrict__ bsg,      // [128]
    const float* __restrict__ eps,      // [T-1, B, DZ]
    float* __restrict__ out,            // mu [B,T,DZ] ++ sigma [B,T,DZ]
    int use_cluster)
{
    extern __shared__ float sm[];
    float* Wg = sm + WG_OFF;
    float* W2 = sm + W2_OFF;
    float* S  = sm + S_OFF;
    ull*   P2 = reinterpret_cast<ull*>(S);   // phase2 partials: 512 ull = rows 0..28

    const int tid = threadIdx.x;
    const int cta = blockIdx.x;
    const int grp = cta >> 4;          // batch group / cluster 0..7
    const int cg  = cta & 15;          // CTA in group (unit / z-col slice)
    const int gb0 = grp * GB;          // first batch row
    const int u0  = cg * 16;           // first unit
    const int slot = grp * 32;

    // ---- one-time: gate weights [k][uu*4+g] ----
    for (int i = tid; i < 512 * 16; i += NTHR) {
        const int k = i >> 4, uu = i & 15;
        const float* src = (k < 256) ? (Wk + (size_t)k * NG)
                                     : (Wr + (size_t)(k - 256) * NG);
        #pragma unroll
        for (int g = 0; g < 4; ++g)
            Wg[k * 64 + uu * 4 + g] = src[g * 256 + u0 + uu];
    }
    // ---- one-time: head weights rows r = zc*2+head, cols u ----
    for (int i = tid; i < 16 * 256; i += NTHR) {
        const int r = i >> 8, u = i & 255;
        const int zc = r >> 1, head = r & 1;
        const int zcg = cg * 8 + zc;
        W2[r * 260 + u] = head ? Wsg[(size_t)u * DZ + zcg]
                               : Wmu[(size_t)u * DZ + zcg];
    }
    // ---- init S: zero z rows and h rows; stage x(0) into x rows ----
    for (int i = tid; i < 128 * 36; i += NTHR) S[i] = 0.0f;               // z
    for (int i = tid; i < 256 * 36; i += NTHR) S[256 * 36 + i] = 0.0f;    // h
    {
        const int xc = tid >> 2, b8x = (tid & 3) * 8;
        float* dst = S + (128 + xc) * 36 + b8x;
        #pragma unroll
        for (int r = 0; r < 8; ++r)
            dst[r] = __ldg(inputs + (size_t)(gb0 + b8x + r) * (TST * DX) + xc);
    }

    // ---- phase1 GEMM identity (R6-proven mapping) ----
    const int warp = tid >> 5, lane = tid & 31;
    const int ks     = warp >> 1;                        // 0..7
    const int ulocal = (warp & 1) * 8 + ((lane >> 2) & 7);
    const int b8     = (lane & 3) * 8;
    const int k0     = ks * 64;

    // ---- reducer identity (tid < 256): (b-pair rbp, unit ru) ----
    const int rbp = tid >> 4;
    const int ru  = tid & 15;
    const int rug = u0 + ru;
    float bi = 0.f, bf = 0.f, bg_ = 0.f, bo = 0.f;
    if (tid < 256) {
        bi  = bias[rug];       bf = bias[256 + rug];
        bg_ = bias[512 + rug]; bo = bias[768 + rug];
    }
    const float* rbase = S + (((ru >> 3) * 32) + ((ru & 7) * 4) + (rbp >> 2)) * 36
                           + (rbp & 3) * 8;
    float c0 = 0.0f, c1 = 0.0f;

    // ---- phase2 identity: warp w: zc=w&7, khalf=w>>3; lane: head,bp ----
    const int p2_zc   = warp & 7;
    const int p2_kh   = warp >> 3;
    const int p2_head = lane >> 4;
    const int p2_bp   = lane & 15;
    const int zcg     = cg * 8 + p2_zc;
    const float bh2   = p2_head ? bsg[zcg] : bmu[zcg];

    __syncthreads();

    unsigned nb = 0;

    for (int t = 0; t < TST; ++t) {
        // ============ PHASE 1: gates GEMM (reads S entirely from SMEM) ==========
        ull a[16];
        #pragma unroll
        for (int i = 0; i < 16; ++i) a[i] = 0ULL;
        {
            const float* wptr = Wg + k0 * 64 + ulocal * 4;
            const float* sptr = S + k0 * 36 + b8;
            #pragma unroll 2
            for (int kk = 0; kk < 64; ++kk) {
                const float4 w4 = *reinterpret_cast<const float4*>(wptr);
                const ulonglong2 sA = *reinterpret_cast<const ulonglong2*>(sptr);
                const ulonglong2 sB = *reinterpret_cast<const ulonglong2*>(sptr + 4);
                wptr += 64; sptr += 36;
                const ull d0 = pack2(w4.x, w4.x);
                const ull d1 = pack2(w4.y, w4.y);
                const ull d2 = pack2(w4.z, w4.z);
                const ull d3 = pack2(w4.w, w4.w);
                ffma2(a[0],  sA.x, d0); ffma2(a[1],  sA.x, d1);
                ffma2(a[2],  sA.x, d2); ffma2(a[3],  sA.x, d3);
                ffma2(a[4],  sA.y, d0); ffma2(a[5],  sA.y, d1);
                ffma2(a[6],  sA.y, d2); ffma2(a[7],  sA.y, d3);
                ffma2(a[8],  sB.x, d0); ffma2(a[9],  sB.x, d1);
                ffma2(a[10], sB.x, d2); ffma2(a[11], sB.x, d3);
                ffma2(a[12], sB.y, d0); ffma2(a[13], sB.y, d1);
                ffma2(a[14], sB.y, d2); ffma2(a[15], sB.y, d3);
            }
        }
        __syncthreads();     // all S reads done -> whole S becomes partials

        // partials write + prefetch x(t+1) and eps(t) into registers
        {
            float* dst = S + tid * 36;
            #pragma unroll
            for (int i = 0; i < 8; ++i) {
                ulonglong2 v; v.x = a[2 * i]; v.y = a[2 * i + 1];
                *reinterpret_cast<ulonglong2*>(dst + i * 4) = v;
            }
        }
        float xr[8];
        const int xc = tid >> 2, b8x = (tid & 3) * 8;
        if (t + 1 < TST) {
            const float* xs = inputs + (size_t)(gb0 + b8x) * (TST * DX)
                                     + (size_t)(t + 1) * DX + xc;
            #pragma unroll
            for (int r = 0; r < 8; ++r)
                xr[r] = __ldg(xs + (size_t)r * (TST * DX));
        }
        float e0 = 0.f, e1 = 0.f;
        if (tid < 256 && p2_head == 0 && t < TST - 1) {
            const float* ep = eps + (size_t)t * (BATCH * DZ)
                                  + (size_t)(gb0 + p2_bp * 2) * DZ + zcg;
            e0 = ld_cg(ep); e1 = ld_cg(ep + DZ);
        }
        __syncthreads();

        // ============ k-split reduction + LSTM update (tid < 256) ==============
        if (tid < 256) {
            ull r0 = 0ULL, r1 = 0ULL, r2 = 0ULL, r3 = 0ULL;
            const float* p = rbase;
            #pragma unroll
            for (int s = 0; s < 8; ++s) {
                const ulonglong2 q0 = *reinterpret_cast<const ulonglong2*>(p);
                const ulonglong2 q1 = *reinterpret_cast<const ulonglong2*>(p + 4);
                fadd2(r0, q0.x); fadd2(r1, q0.y);
                fadd2(r2, q1.x); fadd2(r3, q1.y);
                p += 2 * 32 * 36;
            }
            float i0, i1, f0, f1, gg0, gg1, o0, o1;
            unpack2(r0, i0, i1); unpack2(r1, f0, f1);
            unpack2(r2, gg0, gg1); unpack2(r3, o0, o1);

            c0 = sigmoidf_acc(f0 + bf) * c0 + sigmoidf_acc(i0 + bi) * tanhf(gg0 + bg_);
            c1 = sigmoidf_acc(f1 + bf) * c1 + sigmoidf_acc(i1 + bi) * tanhf(gg1 + bg_);
            const float h0 = sigmoidf_acc(o0 + bo) * tanhf(c0);
            const float h1 = sigmoidf_acc(o1 + bo) * tanhf(c1);
            st_cg_f2(g_H + (size_t)rug * BATCH + gb0 + rbp * 2, h0, h1);
        }
        __syncthreads();     // partial reads complete before x overwrites them

        // ============ group barrier #1 (h visible); overlap x-tile store ======
        if (use_cluster) {
            cbar_arrive();
            if (t + 1 < TST) {
                float* dst = S + (128 + xc) * 36 + b8x;
                *reinterpret_cast<float4*>(dst)     = make_float4(xr[0], xr[1], xr[2], xr[3]);
                *reinterpret_cast<float4*>(dst + 4) = make_float4(xr[4], xr[5], xr[6], xr[7]);
            }
            cbar_wait();
        } else {
            if (t + 1 < TST) {
                float* dst = S + (128 + xc) * 36 + b8x;
                *reinterpret_cast<float4*>(dst)     = make_float4(xr[0], xr[1], xr[2], xr[3]);
                *reinterpret_cast<float4*>(dst + 4) = make_float4(xr[4], xr[5], xr[6], xr[7]);
            }
            fb_sync(slot, ++nb);
        }

        // ============ stage h(t) transposed into S h-rows (vectorized) ========
        {
            const int j = tid >> 1, hh = (tid & 1) * 16;
            const float* src = g_H + (size_t)j * BATCH + gb0 + hh;
            float* dst = S + (256 + j) * 36 + hh;
            #pragma unroll
            for (int r = 0; r < 4; ++r)
                *reinterpret_cast<float4*>(dst + r * 4) = ld_cg_f4(src + r * 4);
        }
        __syncthreads();

        // ============ PHASE 2: heads GEMM from transposed h tile ==============
        ull acc2 = 0ULL;
        {
            const float* sp2 = S + (256 + p2_kh * 128) * 36 + p2_bp * 2;
            const float* wp2 = W2 + (p2_zc * 2 + p2_head) * 260 + p2_kh * 128;
            #pragma unroll 4
            for (int kk = 0; kk < 128; ++kk) {
                const ull hp = *reinterpret_cast<const ull*>(sp2);
                const float wv = wp2[kk];
                ffma2(acc2, hp, pack2(wv, wv));
                sp2 += 36;
            }
        }
        P2[tid] = acc2;        // rows 0..28 of S (z rows; re-staged later)
        __syncthreads();

        if (tid < 256) {       // warps 0..7: combine k-halves, finalize
            ull mine = P2[tid];
            fadd2(mine, P2[tid + 256]);
            float v0, v1; unpack2(mine, v0, v1);
            v0 += bh2; v1 += bh2;
            if (p2_head) {
                v0 = fmaxf(v0, 0.0f) + log1pf(expf(-fabsf(v0))) + 1e-6f;
                v1 = fmaxf(v1, 0.0f) + log1pf(expf(-fabsf(v1))) + 1e-6f;
            }
            // mu <-> sigma exchange within warp (head is lane bit 4)
            const float o0 = __shfl_xor_sync(0xffffffffu, v0, 16);
            const float o1 = __shfl_xor_sync(0xffffffffu, v1, 16);

            const int brow = gb0 + p2_bp * 2;
            float* ob = out + (p2_head ? (size_t)BATCH * TST * DZ : 0)
                            + (size_t)brow * (TST * DZ) + (size_t)t * DZ + zcg;
            ob[0] = v0;
            ob[TST * DZ] = v1;

            if (!p2_head && t < TST - 1) {
                st_cg_f2(g_Z + (size_t)zcg * BATCH + brow,
                         fmaf(o0, e0, v0), fmaf(o1, e1, v1));
            }
        }

        // ============ group barrier #2 (z visible) ============================
        if (use_cluster) {
            cbar_arrive();
            cbar_wait();
        } else {
            fb_sync(slot, ++nb);
        }

        // ============ stage z(t) transposed into S z-rows (vectorized) ========
        {
            const int zc = tid >> 2, q = (tid & 3) * 8;
            const float* src = g_Z + (size_t)zc * BATCH + gb0 + q;
            float* dst = S + zc * 36 + q;
            *reinterpret_cast<float4*>(dst)     = ld_cg_f4(src);
            *reinterpret_cast<float4*>(dst + 4) = ld_cg_f4(src + 4);
        }
        __syncthreads();
    }

    // ---- fallback-path barrier state reset for graph replay ----
    if (!use_cluster && tid == 0) {
        __threadfence();
        const unsigned d = atomicAdd(&g_done[slot], 1u) + 1u;
        if (d == CPG) {
            g_cnt[slot]  = 0;
            g_done[slot] = 0;
            g_gen[slot]  = 0;
            __threadfence();
        }
    }
}

extern "C" void kernel_launch(void* const* d_in, const int* in_sizes, int n_in,
                              void* d_out, int out_size) {
    (void)in_sizes; (void)n_in; (void)out_size;
    const float* inputs = (const float*)d_in[0];
    const float* Wk     = (const float*)d_in[1];
    const float* Wr     = (const float*)d_in[2];
    const float* bias   = (const float*)d_in[3];
    const float* Wmu    = (const float*)d_in[4];
    const float* bmu    = (const float*)d_in[5];
    const float* Wsg    = (const float*)d_in[6];
    const float* bsg    = (const float*)d_in[7];
    const float* eps    = (const float*)d_in[8];
    float* out          = (float*)d_out;

    const size_t smem_bytes = (size_t)SM_FLOATS * sizeof(float);  // 221440 B
    cudaFuncSetAttribute(fused_lstm_persistent,
                         cudaFuncAttributeMaxDynamicSharedMemorySize,
                         (int)smem_bytes);
    cudaFuncSetAttribute(fused_lstm_persistent,
                         cudaFuncAttributeNonPortableClusterSizeAllowed, 1);

    cudaLaunchConfig_t cfg = {};
    cfg.gridDim  = dim3(NCTA, 1, 1);
    cfg.blockDim = dim3(NTHR, 1, 1);
    cfg.dynamicSmemBytes = smem_bytes;
    cfg.stream = 0;
    cudaLaunchAttribute attrs[1];
    attrs[0].id = cudaLaunchAttributeClusterDimension;
    attrs[0].val.clusterDim.x = CPG;
    attrs[0].val.clusterDim.y = 1;
    attrs[0].val.clusterDim.z = 1;
    cfg.attrs = attrs;
    cfg.numAttrs = 1;

    int maxClusters = 0;
    cudaError_t q = cudaOccupancyMaxActiveClusters(&maxClusters,
                                                   fused_lstm_persistent, &cfg);
    bool cluster_ok = (q == cudaSuccess && maxClusters >= NGRP);
    if (cluster_ok) {
        cudaError_t e = cudaLaunchKernelEx(&cfg, fused_lstm_persistent,
                                           inputs, Wk, Wr, bias, Wmu, bmu,
                                           Wsg, bsg, eps, out, 1);
        if (e == cudaSuccess) return;
        cudaGetLastError();
    }
    cudaGetLastError();
    fused_lstm_persistent<<<NCTA, NTHR, smem_bytes>>>(
        inputs, Wk, Wr, bias, Wmu, bmu, Wsg, bsg, eps, out, 0);
}